// round 10
// baseline (speedup 1.0000x reference)
#include <cuda_runtime.h>
#include <math.h>
#include <stdint.h>

// Problem constants
#define B_   32
#define IU_  16
#define IC_  2048
#define NU_  16
#define US_  64
#define ICH  64            // chunks over i
#define CH   (IC_/ICH)     // 32 i per chunk

// Scratch (device globals: allocation-free)
__device__ uint32_t g_Apk[(size_t)IC_ * 4 * 32 * 4];           // 4 MB, tf32 bits, mma A-frag order
__device__ float    g_part[(size_t)ICH * B_ * NU_ * US_];      // 8 MB [chunk][b][j][k]

// ---------------------------------------------------------------------------
__device__ __forceinline__ uint32_t f2tf(float f) {
    uint32_t r;
    asm("cvt.rna.tf32.f32 %0, %1;" : "=r"(r) : "f"(f));
    return r;
}

// ---------------------------------------------------------------------------
// Kernel 1: repack x[b][u][i] into mma A-fragment order, pre-converted to tf32.
// grid 512, block 256; 4 i per block (short blocks -> latency pipelining).
// ---------------------------------------------------------------------------
__global__ void prep_kernel(const float* __restrict__ x) {
    __shared__ float xs[B_][IU_][5];          // il<4, pad to 5
    const int i0 = blockIdx.x * 4;

    // phase 1: 512 (b,u) rows x 1 float4 (i0..i0+3), 2 per thread
    for (int q = threadIdx.x; q < 512; q += 256) {
        int b = q >> 4, u = q & 15;
        float4 v = *(const float4*)(x + ((size_t)b * IU_ + u) * IC_ + i0);
        xs[b][u][0] = v.x; xs[b][u][1] = v.y;
        xs[b][u][2] = v.z; xs[b][u][3] = v.w;
    }
    __syncthreads();

    // phase 2: 4 i x 4 slots x 32 lanes uint4 (tf32), coalesced, 2 per thread
    for (int q = threadIdx.x; q < 512; q += 256) {
        int lane = q & 31;
        int slot = (q >> 5) & 3;
        int il   = q >> 7;                    // 0..3
        int t  = slot >> 1, mt = slot & 1;
        int b0 = (lane >> 2) + 16 * mt;
        int u0 = 4 * (lane & 3) + 2 * t;
        uint4 v;
        v.x = f2tf(xs[b0    ][u0    ][il]);
        v.y = f2tf(xs[b0 + 8][u0    ][il]);
        v.z = f2tf(xs[b0    ][u0 + 1][il]);
        v.w = f2tf(xs[b0 + 8][u0 + 1][il]);
        *(uint4*)(g_Apk + (((size_t)(i0 + il) * 4 + slot) * 32 + lane) * 4) = v;
    }
}

// ---------------------------------------------------------------------------
__device__ __forceinline__ void mma_tf32(float c[4], uint4 a,
                                         uint32_t b0, uint32_t b1) {
    asm volatile(
        "mma.sync.aligned.m16n8k8.row.col.f32.tf32.tf32.f32 "
        "{%0,%1,%2,%3}, {%4,%5,%6,%7}, {%8,%9}, {%0,%1,%2,%3};"
        : "+f"(c[0]), "+f"(c[1]), "+f"(c[2]), "+f"(c[3])
        : "r"(a.x), "r"(a.y), "r"(a.z), "r"(a.w), "r"(b0), "r"(b1));
}

__device__ __forceinline__ float4 ldcs4(const float4* p) {
    float4 v;
    asm volatile("ld.global.cs.v4.f32 {%0,%1,%2,%3}, [%4];"
                 : "=f"(v.x), "=f"(v.y), "=f"(v.z), "=f"(v.w) : "l"(p));
    return v;
}

// ---------------------------------------------------------------------------
// Kernel 2: tf32 GEMM partials. grid (ICH=64, 8 j-pairs), block 256 (8 warps).
// Warp w: kc block = 8w, handles j0 and j0+1. W streamed evict-first with a
// DEPTH-4 register pipeline (8 LDG.128 in flight/warp -> ~64 KB/SM, above the
// ~27 KB needed to saturate HBM). A (tf32, L1/L2-resident) at depth 2.
// ---------------------------------------------------------------------------
__global__ void __launch_bounds__(256, 2) gemm_kernel(const float* __restrict__ W) {
    const int j0    = blockIdx.y * 2;
    const int chunk = blockIdx.x;
    const int i0    = chunk * CH;
    const int warp  = threadIdx.x >> 5;
    const int lane  = threadIdx.x & 31;
    const int kc0   = warp * 8;

    float cA0[4] = {0,0,0,0}, cA1[4] = {0,0,0,0};   // j0   (mt=0 / mt=1)
    float cB0[4] = {0,0,0,0}, cB1[4] = {0,0,0,0};   // j0+1

    const float4* __restrict__ bp =
        (const float4*)(W + (((size_t)i0 * NU_ + j0) * US_ + kc0) * IU_) + lane;
    const uint4* __restrict__ ap =
        (const uint4*)(g_Apk) + (size_t)i0 * 128 + lane;

    float4 wA[4], wB[4];
    uint4  a0[2], a1[2], a2[2], a3[2];

    #pragma unroll
    for (int s = 0; s < 4; ++s) {
        wA[s] = ldcs4(bp + (size_t)s * 4096);
        wB[s] = ldcs4(bp + (size_t)s * 4096 + 256);
    }
    #pragma unroll
    for (int s = 0; s < 2; ++s) {
        a0[s] = ap[s * 128 +  0];
        a1[s] = ap[s * 128 + 32];
        a2[s] = ap[s * 128 + 64];
        a3[s] = ap[s * 128 + 96];
    }

    #pragma unroll 4
    for (int ii = 0; ii < CH; ++ii) {
        float4 bA = wA[ii & 3], bB = wB[ii & 3];
        uint4  A0 = a0[ii & 1], A1 = a1[ii & 1];
        uint4  A2 = a2[ii & 1], A3 = a3[ii & 1];

        if (ii + 4 < CH) {
            const size_t wo = (size_t)(ii + 4) * 4096;
            wA[ii & 3] = ldcs4(bp + wo);
            wB[ii & 3] = ldcs4(bp + wo + 256);
        }
        if (ii + 2 < CH) {
            const int ao = (ii + 2) * 128;
            a0[ii & 1] = ap[ao +  0];
            a1[ii & 1] = ap[ao + 32];
            a2[ii & 1] = ap[ao + 64];
            a3[ii & 1] = ap[ao + 96];
        }

        uint32_t btA[4] = { f2tf(bA.x), f2tf(bA.y), f2tf(bA.z), f2tf(bA.w) };
        uint32_t btB[4] = { f2tf(bB.x), f2tf(bB.y), f2tf(bB.z), f2tf(bB.w) };

        mma_tf32(cA0, A0, btA[0], btA[1]);
        mma_tf32(cA1, A1, btA[0], btA[1]);
        mma_tf32(cA0, A2, btA[2], btA[3]);
        mma_tf32(cA1, A3, btA[2], btA[3]);
        mma_tf32(cB0, A0, btB[0], btB[1]);
        mma_tf32(cB1, A1, btB[0], btB[1]);
        mma_tf32(cB0, A2, btB[2], btB[3]);
        mma_tf32(cB1, A3, btB[2], btB[3]);
    }

    const int brow = lane >> 2;
    const int kc   = kc0 + 2 * (lane & 3);
    const size_t bstr = (size_t)NU_ * US_;
    const size_t baseA = ((size_t)chunk * B_ * NU_ + j0) * US_ + kc;
    const size_t baseB = baseA + US_;

    *(float2*)(g_part + baseA + (brow     ) * bstr) = make_float2(cA0[0], cA0[1]);
    *(float2*)(g_part + baseA + (brow +  8) * bstr) = make_float2(cA0[2], cA0[3]);
    *(float2*)(g_part + baseA + (brow + 16) * bstr) = make_float2(cA1[0], cA1[1]);
    *(float2*)(g_part + baseA + (brow + 24) * bstr) = make_float2(cA1[2], cA1[3]);
    *(float2*)(g_part + baseB + (brow     ) * bstr) = make_float2(cB0[0], cB0[1]);
    *(float2*)(g_part + baseB + (brow +  8) * bstr) = make_float2(cB0[2], cB0[3]);
    *(float2*)(g_part + baseB + (brow + 16) * bstr) = make_float2(cB1[0], cB1[1]);
    *(float2*)(g_part + baseB + (brow + 24) * bstr) = make_float2(cB1[2], cB1[3]);
}

// ---------------------------------------------------------------------------
// Kernel 3: fused reduce-over-64-chunks + squash + writeout.
// grid (B_, 4 k-quarters) = 128 blocks, block (16 k, 16 j) = 256 threads.
// ---------------------------------------------------------------------------
__global__ void squash_kernel(float* __restrict__ out) {
    __shared__ float vbuf[NU_][17];
    __shared__ float fbuf[16];
    const int b  = blockIdx.x;
    const int kq = blockIdx.y;
    const int kl = threadIdx.x;           // 0..15
    const int j  = threadIdx.y;           // 0..15
    const int k  = kq * 16 + kl;

    const float* __restrict__ p =
        g_part + ((size_t)b * NU_ + j) * US_ + k;
    float s = 0.f;
    #pragma unroll
    for (int c = 0; c < ICH; ++c)
        s += p[(size_t)c * (B_ * NU_ * US_)];

    vbuf[j][kl] = s;
    __syncthreads();

    if (j == 0) {
        float msq = 0.f;
        #pragma unroll
        for (int jj = 0; jj < NU_; ++jj) {
            float t = vbuf[jj][kl];
            msq += t * t;
        }
        fbuf[kl] = sqrtf(msq) / (1.0f + msq);
    }
    __syncthreads();

    out[((size_t)b * NU_ + j) * US_ + k] = s * fbuf[kl];
}

// ---------------------------------------------------------------------------
extern "C" void kernel_launch(void* const* d_in, const int* in_sizes, int n_in,
                              void* d_out, int out_size) {
    const float* x = (const float*)d_in[0];
    const float* W = (const float*)d_in[1];
    if (in_sizes[0] != B_ * IU_ * IC_) { const float* t = x; x = W; W = t; }

    prep_kernel<<<IC_ / 4, 256>>>(x);
    gemm_kernel<<<dim3(ICH, NU_ / 2), 256>>>(W);
    squash_kernel<<<dim3(B_, 4), dim3(16, 16)>>>((float*)d_out);
}

// round 11
// speedup vs baseline: 1.0699x; 1.0699x over previous
#include <cuda_runtime.h>
#include <math.h>
#include <stdint.h>

// Problem constants
#define B_   32
#define IU_  16
#define IC_  2048
#define NU_  16
#define US_  64
#define ICH  32            // chunks over i
#define CH   (IC_/ICH)     // 64 i per chunk

// Scratch (device globals: allocation-free)
__device__ uint32_t g_Apk[(size_t)IC_ * 4 * 32 * 4];           // 4 MB, tf32 bits, mma A-frag order
__device__ float    g_part[(size_t)ICH * B_ * NU_ * US_];      // 4 MB [chunk][b][j][k]

// ---------------------------------------------------------------------------
__device__ __forceinline__ uint32_t f2tf(float f) {
    uint32_t r;
    asm("cvt.rna.tf32.f32 %0, %1;" : "=r"(r) : "f"(f));
    return r;
}

// ---------------------------------------------------------------------------
// Kernel 1: repack x[b][u][i] -> mma A-fragment order (tf32 bits).
// grid 128, block 512; 16 i per block.
// Phase 1 is sector-coalesced: 4 lanes share one 64 B row segment.
// ---------------------------------------------------------------------------
__global__ void __launch_bounds__(512, 1) prep_kernel(const float* __restrict__ x) {
    __shared__ float xs[512][17];             // [(b,u) row][i_local], pad 17
    const int i0  = blockIdx.x * 16;
    const int tid = threadIdx.x;

    // phase 1: 512 rows x 16 floats (4 float4 each) = 2048 float4, 4/thread
    #pragma unroll
    for (int p = 0; p < 4; ++p) {
        int q   = tid + p * 512;
        int row = q >> 2;                     // (b,u) row = b*16+u
        int f   = q & 3;
        float4 v = *(const float4*)(x + (size_t)row * IC_ + i0 + f * 4);
        xs[row][f*4+0] = v.x; xs[row][f*4+1] = v.y;
        xs[row][f*4+2] = v.z; xs[row][f*4+3] = v.w;
    }
    __syncthreads();

    // phase 2: 16 i x 4 slots x 32 lanes uint4, coalesced stores, 4/thread
    #pragma unroll
    for (int p = 0; p < 4; ++p) {
        int q    = tid + p * 512;
        int lane = q & 31;
        int slot = (q >> 5) & 3;
        int il   = q >> 7;                    // 0..15
        int t  = slot >> 1, mt = slot & 1;
        int b0 = (lane >> 2) + 16 * mt;
        int u0 = 4 * (lane & 3) + 2 * t;
        int r00 = b0 * IU_ + u0;
        int r10 = r00 + 8 * IU_;
        uint4 v;
        v.x = f2tf(xs[r00    ][il]);
        v.y = f2tf(xs[r10    ][il]);
        v.z = f2tf(xs[r00 + 1][il]);
        v.w = f2tf(xs[r10 + 1][il]);
        *(uint4*)(g_Apk + (((size_t)(i0 + il) * 4 + slot) * 32 + lane) * 4) = v;
    }
}

// ---------------------------------------------------------------------------
__device__ __forceinline__ void mma_tf32(float c[4], uint4 a,
                                         uint32_t b0, uint32_t b1) {
    asm volatile(
        "mma.sync.aligned.m16n8k8.row.col.f32.tf32.tf32.f32 "
        "{%0,%1,%2,%3}, {%4,%5,%6,%7}, {%8,%9}, {%0,%1,%2,%3};"
        : "+f"(c[0]), "+f"(c[1]), "+f"(c[2]), "+f"(c[3])
        : "r"(a.x), "r"(a.y), "r"(a.z), "r"(a.w), "r"(b0), "r"(b1));
}

__device__ __forceinline__ float4 ldcs4(const float4* p) {
    float4 v;
    asm volatile("ld.global.cs.v4.f32 {%0,%1,%2,%3}, [%4];"
                 : "=f"(v.x), "=f"(v.y), "=f"(v.z), "=f"(v.w) : "l"(p));
    return v;
}

// ---------------------------------------------------------------------------
// Kernel 2: tf32 GEMM partials. grid (ICH=32, 8 j-pairs) = 256 blocks = one
// wave at occ 2. Warp w: kc block = 8w, handles j0/j0+1. Depth-2 W pipeline
// (4 LDG.128 in flight/warp ~ 32 KB/SM > 27 KB HBM requirement), A depth-2.
// ---------------------------------------------------------------------------
__global__ void __launch_bounds__(256, 2) gemm_kernel(const float* __restrict__ W) {
    const int j0    = blockIdx.y * 2;
    const int chunk = blockIdx.x;
    const int i0    = chunk * CH;
    const int warp  = threadIdx.x >> 5;
    const int lane  = threadIdx.x & 31;
    const int kc0   = warp * 8;

    float cA0[4] = {0,0,0,0}, cA1[4] = {0,0,0,0};   // j0   (mt=0 / mt=1)
    float cB0[4] = {0,0,0,0}, cB1[4] = {0,0,0,0};   // j0+1

    const float4* __restrict__ bp =
        (const float4*)(W + (((size_t)i0 * NU_ + j0) * US_ + kc0) * IU_) + lane;
    const uint4* __restrict__ ap =
        (const uint4*)(g_Apk) + (size_t)i0 * 128 + lane;

    float4 wA[2], wB[2];
    uint4  a0[2], a1[2], a2[2], a3[2];

    #pragma unroll
    for (int s = 0; s < 2; ++s) {
        wA[s] = ldcs4(bp + (size_t)s * 4096);
        wB[s] = ldcs4(bp + (size_t)s * 4096 + 256);
        a0[s] = ap[s * 128 +  0];
        a1[s] = ap[s * 128 + 32];
        a2[s] = ap[s * 128 + 64];
        a3[s] = ap[s * 128 + 96];
    }

    #pragma unroll 4
    for (int ii = 0; ii < CH; ++ii) {
        float4 bA = wA[ii & 1], bB = wB[ii & 1];
        uint4  A0 = a0[ii & 1], A1 = a1[ii & 1];
        uint4  A2 = a2[ii & 1], A3 = a3[ii & 1];

        if (ii + 2 < CH) {
            const size_t wo = (size_t)(ii + 2) * 4096;
            const int    ao = (ii + 2) * 128;
            wA[ii & 1] = ldcs4(bp + wo);
            wB[ii & 1] = ldcs4(bp + wo + 256);
            a0[ii & 1] = ap[ao +  0];
            a1[ii & 1] = ap[ao + 32];
            a2[ii & 1] = ap[ao + 64];
            a3[ii & 1] = ap[ao + 96];
        }

        uint32_t btA[4] = { f2tf(bA.x), f2tf(bA.y), f2tf(bA.z), f2tf(bA.w) };
        uint32_t btB[4] = { f2tf(bB.x), f2tf(bB.y), f2tf(bB.z), f2tf(bB.w) };

        mma_tf32(cA0, A0, btA[0], btA[1]);
        mma_tf32(cA1, A1, btA[0], btA[1]);
        mma_tf32(cA0, A2, btA[2], btA[3]);
        mma_tf32(cA1, A3, btA[2], btA[3]);
        mma_tf32(cB0, A0, btB[0], btB[1]);
        mma_tf32(cB1, A1, btB[0], btB[1]);
        mma_tf32(cB0, A2, btB[2], btB[3]);
        mma_tf32(cB1, A3, btB[2], btB[3]);
    }

    const int brow = lane >> 2;
    const int kc   = kc0 + 2 * (lane & 3);
    const size_t bstr = (size_t)NU_ * US_;
    const size_t baseA = ((size_t)chunk * B_ * NU_ + j0) * US_ + kc;
    const size_t baseB = baseA + US_;

    *(float2*)(g_part + baseA + (brow     ) * bstr) = make_float2(cA0[0], cA0[1]);
    *(float2*)(g_part + baseA + (brow +  8) * bstr) = make_float2(cA0[2], cA0[3]);
    *(float2*)(g_part + baseA + (brow + 16) * bstr) = make_float2(cA1[0], cA1[1]);
    *(float2*)(g_part + baseA + (brow + 24) * bstr) = make_float2(cA1[2], cA1[3]);
    *(float2*)(g_part + baseB + (brow     ) * bstr) = make_float2(cB0[0], cB0[1]);
    *(float2*)(g_part + baseB + (brow +  8) * bstr) = make_float2(cB0[2], cB0[3]);
    *(float2*)(g_part + baseB + (brow + 16) * bstr) = make_float2(cB1[0], cB1[1]);
    *(float2*)(g_part + baseB + (brow + 24) * bstr) = make_float2(cB1[2], cB1[3]);
}

// ---------------------------------------------------------------------------
// Kernel 3: fused reduce-over-32-chunks + squash + writeout.
// grid (B_, 4 k-quarters) = 128 blocks, block (16 k, 16 j) = 256 threads.
// ---------------------------------------------------------------------------
__global__ void squash_kernel(float* __restrict__ out) {
    __shared__ float vbuf[NU_][17];
    __shared__ float fbuf[16];
    const int b  = blockIdx.x;
    const int kq = blockIdx.y;
    const int kl = threadIdx.x;           // 0..15
    const int j  = threadIdx.y;           // 0..15
    const int k  = kq * 16 + kl;

    const float* __restrict__ p =
        g_part + ((size_t)b * NU_ + j) * US_ + k;
    float s = 0.f;
    #pragma unroll
    for (int c = 0; c < ICH; ++c)
        s += p[(size_t)c * (B_ * NU_ * US_)];

    vbuf[j][kl] = s;
    __syncthreads();

    if (j == 0) {
        float msq = 0.f;
        #pragma unroll
        for (int jj = 0; jj < NU_; ++jj) {
            float t = vbuf[jj][kl];
            msq += t * t;
        }
        fbuf[kl] = sqrtf(msq) / (1.0f + msq);
    }
    __syncthreads();

    out[((size_t)b * NU_ + j) * US_ + k] = s * fbuf[kl];
}

// ---------------------------------------------------------------------------
extern "C" void kernel_launch(void* const* d_in, const int* in_sizes, int n_in,
                              void* d_out, int out_size) {
    const float* x = (const float*)d_in[0];
    const float* W = (const float*)d_in[1];
    if (in_sizes[0] != B_ * IU_ * IC_) { const float* t = x; x = W; W = t; }

    prep_kernel<<<IC_ / 16, 512>>>(x);
    gemm_kernel<<<dim3(ICH, NU_ / 2), 256>>>(W);
    squash_kernel<<<dim3(B_, 4), dim3(16, 16)>>>((float*)d_out);
}

// round 12
// speedup vs baseline: 1.1242x; 1.0508x over previous
#include <cuda_runtime.h>
#include <math.h>
#include <stdint.h>

// Problem constants
#define B_   32
#define IU_  16
#define IC_  2048
#define NU_  16
#define US_  64
#define ICH  64            // chunks over i
#define CH   (IC_/ICH)     // 32 i per chunk

// Scratch (device globals: allocation-free)
__device__ uint32_t g_Apk[(size_t)IC_ * 4 * 32 * 4];           // 4 MB, tf32 bits, mma A-frag order
__device__ float    g_part[(size_t)ICH * B_ * NU_ * US_];      // 8 MB [chunk][b][j][k]

// ---------------------------------------------------------------------------
__device__ __forceinline__ uint32_t f2tf(float f) {
    uint32_t r;
    asm("cvt.rna.tf32.f32 %0, %1;" : "=r"(r) : "f"(f));
    return r;
}

// ---------------------------------------------------------------------------
// Kernel 1: repack x[b][u][i] -> mma A-fragment order (tf32 bits).
// grid (128 i-slabs, 2 b-halves), block 256. Each block: 256 (b,u) rows x 16 i.
// Slot set decomposes exactly by mt = b>>4: block (slab, mt) writes slots
// {mt, mt+2} only -> fully independent half-blocks, 2x parallelism.
// ---------------------------------------------------------------------------
__global__ void __launch_bounds__(256, 2) prep_kernel(const float* __restrict__ x) {
    __shared__ float xs[256][17];             // [local row][i_local]
    const int i0  = blockIdx.x * 16;
    const int mt  = blockIdx.y;               // b-half
    const int tid = threadIdx.x;

    // phase 1: 256 rows x 16 floats (4 float4) = 1024 loads, 4/thread.
    // warp covers 8 rows x 64 B contiguous -> full-sector coalesced.
    #pragma unroll
    for (int p = 0; p < 4; ++p) {
        int q  = tid + p * 256;
        int rl = q >> 2;                      // local row 0..255
        int f  = q & 3;
        float4 v = *(const float4*)(x + (size_t)(mt * 256 + rl) * IC_ + i0 + f * 4);
        xs[rl][f*4+0] = v.x; xs[rl][f*4+1] = v.y;
        xs[rl][f*4+2] = v.z; xs[rl][f*4+3] = v.w;
    }
    __syncthreads();

    // phase 2: 2 t-slots x 32 lanes x 16 il = 1024 uint4 stores, 4/thread.
    #pragma unroll
    for (int p = 0; p < 4; ++p) {
        int q    = tid + p * 256;
        int lane = q & 31;
        int t    = (q >> 5) & 1;
        int il   = q >> 6;                    // 0..15
        int slot = 2 * t + mt;
        int u0   = 4 * (lane & 3) + 2 * t;
        int r00  = (lane >> 2) * 16 + u0;     // local row of (b0, u0)
        uint4 v;
        v.x = f2tf(xs[r00      ][il]);
        v.y = f2tf(xs[r00 + 128][il]);        // b0+8
        v.z = f2tf(xs[r00 +   1][il]);        // u0+1
        v.w = f2tf(xs[r00 + 129][il]);
        *(uint4*)(g_Apk + (((size_t)(i0 + il) * 4 + slot) * 32 + lane) * 4) = v;
    }
}

// ---------------------------------------------------------------------------
__device__ __forceinline__ void mma_tf32(float c[4], uint4 a,
                                         uint32_t b0, uint32_t b1) {
    asm volatile(
        "mma.sync.aligned.m16n8k8.row.col.f32.tf32.tf32.f32 "
        "{%0,%1,%2,%3}, {%4,%5,%6,%7}, {%8,%9}, {%0,%1,%2,%3};"
        : "+f"(c[0]), "+f"(c[1]), "+f"(c[2]), "+f"(c[3])
        : "r"(a.x), "r"(a.y), "r"(a.z), "r"(a.w), "r"(b0), "r"(b1));
}

__device__ __forceinline__ float4 ldcs4(const float4* p) {
    float4 v;
    asm volatile("ld.global.cs.v4.f32 {%0,%1,%2,%3}, [%4];"
                 : "=f"(v.x), "=f"(v.y), "=f"(v.z), "=f"(v.w) : "l"(p));
    return v;
}

// ---------------------------------------------------------------------------
// Kernel 2: tf32 GEMM partials, j-fan-out 4.
// grid (ICH=64, 4 j-quads) = 256 blocks = one occ-2 wave. Warp w: kc block
// = 8w, handles j0..j0+3 -> per ii: 4 W LDG + 4 A LDG for 2 KB of W
// (half the A-load rate of the previous kernel). W depth-2, A depth-1-ahead.
// ---------------------------------------------------------------------------
__global__ void __launch_bounds__(256, 2) gemm_kernel(const float* __restrict__ W) {
    const int j0    = blockIdx.y * 4;
    const int chunk = blockIdx.x;
    const int i0    = chunk * CH;
    const int warp  = threadIdx.x >> 5;
    const int lane  = threadIdx.x & 31;
    const int kc0   = warp * 8;

    // accumulators: [j][mt][4]
    float c0[4][4], c1[4][4];
    #pragma unroll
    for (int d = 0; d < 4; ++d)
        #pragma unroll
        for (int r = 0; r < 4; ++r) { c0[d][r] = 0.f; c1[d][r] = 0.f; }

    const float4* __restrict__ bp =
        (const float4*)(W + (((size_t)i0 * NU_ + j0) * US_ + kc0) * IU_) + lane;
    const uint4* __restrict__ ap =
        (const uint4*)(g_Apk) + (size_t)i0 * 128 + lane;

    // W pipeline depth 2: w[j][buf]
    float4 w[4][2];
    #pragma unroll
    for (int s = 0; s < 2; ++s)
        #pragma unroll
        for (int d = 0; d < 4; ++d)
            w[d][s] = ldcs4(bp + (size_t)s * 4096 + d * 256);

    // A depth-1-ahead
    uint4 na0 = ap[0], na1 = ap[32], na2 = ap[64], na3 = ap[96];

    #pragma unroll 2
    for (int ii = 0; ii < CH; ++ii) {
        // consume current
        float4 bJ[4];
        #pragma unroll
        for (int d = 0; d < 4; ++d) bJ[d] = w[d][ii & 1];
        uint4 A0 = na0, A1 = na1, A2 = na2, A3 = na3;

        // prefetch A(ii+1)
        if (ii + 1 < CH) {
            const int ao = (ii + 1) * 128;
            na0 = ap[ao +  0];
            na1 = ap[ao + 32];
            na2 = ap[ao + 64];
            na3 = ap[ao + 96];
        }
        // prefetch W(ii+2)
        if (ii + 2 < CH) {
            const size_t wo = (size_t)(ii + 2) * 4096;
            #pragma unroll
            for (int d = 0; d < 4; ++d)
                w[d][ii & 1] = ldcs4(bp + wo + d * 256);
        }

        #pragma unroll
        for (int d = 0; d < 4; ++d) {
            uint32_t b0 = f2tf(bJ[d].x), b1 = f2tf(bJ[d].y);
            uint32_t b2 = f2tf(bJ[d].z), b3 = f2tf(bJ[d].w);
            mma_tf32(c0[d], A0, b0, b1);
            mma_tf32(c1[d], A1, b0, b1);
            mma_tf32(c0[d], A2, b2, b3);
            mma_tf32(c1[d], A3, b2, b3);
        }
    }

    const int brow = lane >> 2;
    const int kc   = kc0 + 2 * (lane & 3);
    const size_t bstr = (size_t)NU_ * US_;
    #pragma unroll
    for (int d = 0; d < 4; ++d) {
        const size_t base = ((size_t)chunk * B_ * NU_ + (j0 + d)) * US_ + kc;
        *(float2*)(g_part + base + (brow     ) * bstr) = make_float2(c0[d][0], c0[d][1]);
        *(float2*)(g_part + base + (brow +  8) * bstr) = make_float2(c0[d][2], c0[d][3]);
        *(float2*)(g_part + base + (brow + 16) * bstr) = make_float2(c1[d][0], c1[d][1]);
        *(float2*)(g_part + base + (brow + 24) * bstr) = make_float2(c1[d][2], c1[d][3]);
    }
}

// ---------------------------------------------------------------------------
// Kernel 3: fused reduce-over-64-chunks + squash + writeout.
// grid (B_, 4 k-quarters) = 128 blocks, block (16 k, 16 j) = 256 threads.
// ---------------------------------------------------------------------------
__global__ void squash_kernel(float* __restrict__ out) {
    __shared__ float vbuf[NU_][17];
    __shared__ float fbuf[16];
    const int b  = blockIdx.x;
    const int kq = blockIdx.y;
    const int kl = threadIdx.x;           // 0..15
    const int j  = threadIdx.y;           // 0..15
    const int k  = kq * 16 + kl;

    const float* __restrict__ p =
        g_part + ((size_t)b * NU_ + j) * US_ + k;
    float s = 0.f;
    #pragma unroll 8
    for (int c = 0; c < ICH; ++c)
        s += p[(size_t)c * (B_ * NU_ * US_)];

    vbuf[j][kl] = s;
    __syncthreads();

    if (j == 0) {
        float msq = 0.f;
        #pragma unroll
        for (int jj = 0; jj < NU_; ++jj) {
            float t = vbuf[jj][kl];
            msq += t * t;
        }
        fbuf[kl] = sqrtf(msq) / (1.0f + msq);
    }
    __syncthreads();

    out[((size_t)b * NU_ + j) * US_ + k] = s * fbuf[kl];
}

// ---------------------------------------------------------------------------
extern "C" void kernel_launch(void* const* d_in, const int* in_sizes, int n_in,
                              void* d_out, int out_size) {
    const float* x = (const float*)d_in[0];
    const float* W = (const float*)d_in[1];
    if (in_sizes[0] != B_ * IU_ * IC_) { const float* t = x; x = W; W = t; }

    prep_kernel<<<dim3(IC_ / 16, 2), 256>>>(x);
    gemm_kernel<<<dim3(ICH, NU_ / 4), 256>>>(W);
    squash_kernel<<<dim3(B_, 4), dim3(16, 16)>>>((float*)d_out);
}

// round 15
// speedup vs baseline: 1.1376x; 1.0119x over previous
#include <cuda_runtime.h>
#include <math.h>
#include <stdint.h>

// Problem constants
#define B_   32
#define IU_  16
#define IC_  2048
#define NU_  16
#define US_  64
#define ICH  64            // chunks over i
#define CH   (IC_/ICH)     // 32 i per chunk

// Scratch (device globals: allocation-free)
__device__ uint32_t g_Apk[(size_t)IC_ * 4 * 32 * 4];           // 4 MB, tf32 bits, mma A-frag order
__device__ float    g_part[(size_t)ICH * B_ * NU_ * US_];      // 8 MB [chunk][b][j][k]

// ---------------------------------------------------------------------------
__device__ __forceinline__ uint32_t f2tf(float f) {
    uint32_t r;
    asm("cvt.rna.tf32.f32 %0, %1;" : "=r"(r) : "f"(f));
    return r;
}

// ---------------------------------------------------------------------------
// Kernel 1: repack x[b][u][i] -> mma A-fragment order (tf32 bits).
// grid (256 i-slabs of 8, 2 b-halves) = 512 blocks (R12 was grid-limited @256).
// ---------------------------------------------------------------------------
__global__ void prep_kernel(const float* __restrict__ x) {
    __shared__ float xs[256][9];              // [local row][i_local 0..7]
    const int i0  = blockIdx.x * 8;
    const int mt  = blockIdx.y;               // b-half
    const int tid = threadIdx.x;

    // phase 1: 256 rows x 8 floats (2 float4) = 512 loads, 2/thread
    #pragma unroll
    for (int p = 0; p < 2; ++p) {
        int q  = tid + p * 256;
        int rl = q >> 1;                      // local row 0..255
        int f  = q & 1;
        float4 v = *(const float4*)(x + (size_t)(mt * 256 + rl) * IC_ + i0 + f * 4);
        xs[rl][f*4+0] = v.x; xs[rl][f*4+1] = v.y;
        xs[rl][f*4+2] = v.z; xs[rl][f*4+3] = v.w;
    }
    __syncthreads();

    // phase 2: 2 t-slots x 32 lanes x 8 il = 512 uint4 stores, 2/thread
    #pragma unroll
    for (int p = 0; p < 2; ++p) {
        int q    = tid + p * 256;
        int lane = q & 31;
        int t    = (q >> 5) & 1;
        int il   = q >> 6;                    // 0..7
        int slot = 2 * t + mt;
        int u0   = 4 * (lane & 3) + 2 * t;
        int r00  = (lane >> 2) * 16 + u0;     // local row of (b0, u0)
        uint4 v;
        v.x = f2tf(xs[r00      ][il]);
        v.y = f2tf(xs[r00 + 128][il]);        // b0+8
        v.z = f2tf(xs[r00 +   1][il]);        // u0+1
        v.w = f2tf(xs[r00 + 129][il]);
        *(uint4*)(g_Apk + (((size_t)(i0 + il) * 4 + slot) * 32 + lane) * 4) = v;
    }
}

// ---------------------------------------------------------------------------
__device__ __forceinline__ void mma_tf32(float c[4], uint4 a,
                                         uint32_t b0, uint32_t b1) {
    asm volatile(
        "mma.sync.aligned.m16n8k8.row.col.f32.tf32.tf32.f32 "
        "{%0,%1,%2,%3}, {%4,%5,%6,%7}, {%8,%9}, {%0,%1,%2,%3};"
        : "+f"(c[0]), "+f"(c[1]), "+f"(c[2]), "+f"(c[3])
        : "r"(a.x), "r"(a.y), "r"(a.z), "r"(a.w), "r"(b0), "r"(b1));
}

__device__ __forceinline__ float4 ldcs4(const float4* p) {
    float4 v;
    asm volatile("ld.global.cs.v4.f32 {%0,%1,%2,%3}, [%4];"
                 : "=f"(v.x), "=f"(v.y), "=f"(v.z), "=f"(v.w) : "l"(p));
    return v;
}

// ---------------------------------------------------------------------------
// Kernel 2: tf32 GEMM partials, j-fan-out 4 (register pipeline — R12 version,
// known-good). grid (ICH=64, 4 j-quads) = 256 blocks = one occ-2 wave.
// Warp w: kc block = 8w, handles j0..j0+3. W depth-2, A depth-1-ahead.
// ---------------------------------------------------------------------------
__global__ void __launch_bounds__(256, 2) gemm_kernel(const float* __restrict__ W) {
    const int j0    = blockIdx.y * 4;
    const int chunk = blockIdx.x;
    const int i0    = chunk * CH;
    const int warp  = threadIdx.x >> 5;
    const int lane  = threadIdx.x & 31;
    const int kc0   = warp * 8;

    float c0[4][4], c1[4][4];
    #pragma unroll
    for (int d = 0; d < 4; ++d)
        #pragma unroll
        for (int r = 0; r < 4; ++r) { c0[d][r] = 0.f; c1[d][r] = 0.f; }

    const float4* __restrict__ bp =
        (const float4*)(W + (((size_t)i0 * NU_ + j0) * US_ + kc0) * IU_) + lane;
    const uint4* __restrict__ ap =
        (const uint4*)(g_Apk) + (size_t)i0 * 128 + lane;

    // W pipeline depth 2: w[j][buf]
    float4 w[4][2];
    #pragma unroll
    for (int s = 0; s < 2; ++s)
        #pragma unroll
        for (int d = 0; d < 4; ++d)
            w[d][s] = ldcs4(bp + (size_t)s * 4096 + d * 256);

    // A depth-1-ahead
    uint4 na0 = ap[0], na1 = ap[32], na2 = ap[64], na3 = ap[96];

    #pragma unroll 2
    for (int ii = 0; ii < CH; ++ii) {
        float4 bJ[4];
        #pragma unroll
        for (int d = 0; d < 4; ++d) bJ[d] = w[d][ii & 1];
        uint4 A0 = na0, A1 = na1, A2 = na2, A3 = na3;

        if (ii + 1 < CH) {
            const int ao = (ii + 1) * 128;
            na0 = ap[ao +  0];
            na1 = ap[ao + 32];
            na2 = ap[ao + 64];
            na3 = ap[ao + 96];
        }
        if (ii + 2 < CH) {
            const size_t wo = (size_t)(ii + 2) * 4096;
            #pragma unroll
            for (int d = 0; d < 4; ++d)
                w[d][ii & 1] = ldcs4(bp + wo + d * 256);
        }

        #pragma unroll
        for (int d = 0; d < 4; ++d) {
            uint32_t b0 = f2tf(bJ[d].x), b1 = f2tf(bJ[d].y);
            uint32_t b2 = f2tf(bJ[d].z), b3 = f2tf(bJ[d].w);
            mma_tf32(c0[d], A0, b0, b1);
            mma_tf32(c1[d], A1, b0, b1);
            mma_tf32(c0[d], A2, b2, b3);
            mma_tf32(c1[d], A3, b2, b3);
        }
    }

    const int brow = lane >> 2;
    const int kc   = kc0 + 2 * (lane & 3);
    const size_t bstr = (size_t)NU_ * US_;
    #pragma unroll
    for (int d = 0; d < 4; ++d) {
        const size_t base = ((size_t)chunk * B_ * NU_ + (j0 + d)) * US_ + kc;
        *(float2*)(g_part + base + (brow     ) * bstr) = make_float2(c0[d][0], c0[d][1]);
        *(float2*)(g_part + base + (brow +  8) * bstr) = make_float2(c0[d][2], c0[d][3]);
        *(float2*)(g_part + base + (brow + 16) * bstr) = make_float2(c1[d][0], c1[d][1]);
        *(float2*)(g_part + base + (brow + 24) * bstr) = make_float2(c1[d][2], c1[d][3]);
    }
}

// ---------------------------------------------------------------------------
// Kernel 3: fused reduce-over-64-chunks + squash + writeout.
// grid (B_, 4 k-quarters) = 128 blocks, block (16 k, 16 j) = 256 threads.
// ---------------------------------------------------------------------------
__global__ void squash_kernel(float* __restrict__ out) {
    __shared__ float vbuf[NU_][17];
    __shared__ float fbuf[16];
    const int b  = blockIdx.x;
    const int kq = blockIdx.y;
    const int kl = threadIdx.x;           // 0..15
    const int j  = threadIdx.y;           // 0..15
    const int k  = kq * 16 + kl;

    const float* __restrict__ p =
        g_part + ((size_t)b * NU_ + j) * US_ + k;
    float s = 0.f;
    #pragma unroll 8
    for (int c = 0; c < ICH; ++c)
        s += p[(size_t)c * (B_ * NU_ * US_)];

    vbuf[j][kl] = s;
    __syncthreads();

    if (j == 0) {
        float msq = 0.f;
        #pragma unroll
        for (int jj = 0; jj < NU_; ++jj) {
            float t = vbuf[jj][kl];
            msq += t * t;
        }
        fbuf[kl] = sqrtf(msq) / (1.0f + msq);
    }
    __syncthreads();

    out[((size_t)b * NU_ + j) * US_ + k] = s * fbuf[kl];
}

// ---------------------------------------------------------------------------
extern "C" void kernel_launch(void* const* d_in, const int* in_sizes, int n_in,
                              void* d_out, int out_size) {
    const float* x = (const float*)d_in[0];
    const float* W = (const float*)d_in[1];
    if (in_sizes[0] != B_ * IU_ * IC_) { const float* t = x; x = W; W = t; }

    prep_kernel<<<dim3(IC_ / 8, 2), 256>>>(x);
    gemm_kernel<<<dim3(ICH, NU_ / 4), 256>>>(W);
    squash_kernel<<<dim3(B_, 4), dim3(16, 16)>>>((float*)d_out);
}